// round 4
// baseline (speedup 1.0000x reference)
#include <cuda_runtime.h>
#include <cstdint>

#define BATCH  4
#define SEQ    2048
#define DMODEL 1024
#define NH     16
#define NKV    4
#define HDIM   64
#define NEXP   8
#define FDIM   1024
#define NTOK   (BATCH*SEQ)      // 8192
#define NSLOT  (NTOK*2)         // 16384

// ---------------- device scratch (static, allocation-rule safe) ----------------
__device__ float g_xn [NTOK*DMODEL];
__device__ float g_q  [NTOK*DMODEL];
__device__ float g_o  [NTOK*DMODEL];
__device__ float g_h  [NTOK*DMODEL];
__device__ float g_yn [NTOK*DMODEL];
__device__ float g_moe[NTOK*DMODEL];
__device__ float g_heG[(size_t)NSLOT*FDIM];
__device__ float g_heU[(size_t)NSLOT*FDIM];
__device__ int   g_topk_e[NTOK*2];
__device__ float g_topk_w[NTOK*2];
__device__ int   g_cnt[NEXP];
__device__ int   g_off[NEXP];
__device__ int   g_cur[NEXP];
__device__ int   g_tok[NSLOT];
__device__ float g_gate[NSLOT];

// ---------------- zero moe accumulator + expert counters ----------------
__global__ void zero_kernel(float* moe, int* cnt) {
    int i = blockIdx.x * blockDim.x + threadIdx.x;
    if (i < NTOK*DMODEL) moe[i] = 0.f;
    if (i < NEXP) cnt[i] = 0;
}

// ---------------- RMSNorm: one block per row ----------------
__global__ void rmsnorm_kernel(const float* __restrict__ x, const float* __restrict__ w,
                               float* __restrict__ out) {
    int row = blockIdx.x;
    const float* xr = x + (size_t)row * DMODEL;
    float ss = 0.f;
    for (int d = threadIdx.x; d < DMODEL; d += 256) { float v = xr[d]; ss += v * v; }
    __shared__ float red[8];
    for (int o = 16; o; o >>= 1) ss += __shfl_down_sync(0xffffffffu, ss, o);
    if ((threadIdx.x & 31) == 0) red[threadIdx.x >> 5] = ss;
    __syncthreads();
    if (threadIdx.x < 8) {
        float v = red[threadIdx.x];
        for (int o = 4; o; o >>= 1) v += __shfl_down_sync(0xffu, v, o);
        if (threadIdx.x == 0) red[0] = v;
    }
    __syncthreads();
    float rs = rsqrtf(red[0] / (float)DMODEL + 1e-6f);
    for (int d = threadIdx.x; d < DMODEL; d += 256)
        out[(size_t)row * DMODEL + d] = xr[d] * rs * w[d];
}

// ---------------- SGEMM core: 128x128x8, 256 threads, 8x8 microtile ----------------
// Double-buffered smem: one __syncthreads per K-step, global prefetch overlapped
// with the FMA body.
#define BM 128
#define BN 128
#define BKk 8

// compute body on one smem stage (shared by all GEMM variants)
#define GEMM_COMPUTE(AsS, BsS)                                              \
    _Pragma("unroll")                                                       \
    for (int k = 0; k < BKk; ++k) {                                         \
        float4 a0 = *reinterpret_cast<const float4*>(&AsS[k][ty * 8]);      \
        float4 a1 = *reinterpret_cast<const float4*>(&AsS[k][ty * 8 + 4]);  \
        float4 b0 = *reinterpret_cast<const float4*>(&BsS[k][tx * 8]);      \
        float4 b1 = *reinterpret_cast<const float4*>(&BsS[k][tx * 8 + 4]);  \
        float a[8] = {a0.x,a0.y,a0.z,a0.w,a1.x,a1.y,a1.z,a1.w};             \
        float b[8] = {b0.x,b0.y,b0.z,b0.w,b1.x,b1.y,b1.z,b1.w};             \
        _Pragma("unroll")                                                   \
        for (int i = 0; i < 8; i++)                                         \
            _Pragma("unroll")                                               \
            for (int j = 0; j < 8; j++) acc[i][j] += a[i] * b[j];           \
    }

#define GEMM_STORE_STAGE(st, av, bv)                                        \
    As[st][aCol + 0][aRow] = av.x; As[st][aCol + 1][aRow] = av.y;           \
    As[st][aCol + 2][aRow] = av.z; As[st][aCol + 3][aRow] = av.w;           \
    *reinterpret_cast<float4*>(&Bs[st][bRow][bCol]) = bv;

__global__ __launch_bounds__(256)
void sgemm_kernel(const float* __restrict__ A, const float* __restrict__ B,
                  float* __restrict__ C, int M, int N, int Kd,
                  const float* __restrict__ resid) {
    __shared__ __align__(16) float As[2][BKk][BM];
    __shared__ __align__(16) float Bs[2][BKk][BN];
    int tid = threadIdx.x;
    int m0 = blockIdx.y * BM, n0 = blockIdx.x * BN;
    int aRow = tid >> 1, aCol = (tid & 1) * 4;
    int bRow = tid >> 5, bCol = (tid & 31) * 4;
    const float* Aptr = A + (size_t)(m0 + aRow) * Kd + aCol;
    const float* Bptr = B + (size_t)bRow * N + n0 + bCol;
    int tx = tid & 15, ty = tid >> 4;
    float acc[8][8];
    #pragma unroll
    for (int i = 0; i < 8; i++)
        #pragma unroll
        for (int j = 0; j < 8; j++) acc[i][j] = 0.f;

    // preload stage 0
    {
        float4 av = *reinterpret_cast<const float4*>(Aptr); Aptr += BKk;
        float4 bv = *reinterpret_cast<const float4*>(Bptr); Bptr += (size_t)BKk * N;
        GEMM_STORE_STAGE(0, av, bv)
    }
    __syncthreads();
    int cur = 0;
    for (int k0 = 0; k0 < Kd; k0 += BKk) {
        bool has_next = (k0 + BKk) < Kd;
        float4 av, bv;
        if (has_next) {
            av = *reinterpret_cast<const float4*>(Aptr); Aptr += BKk;
            bv = *reinterpret_cast<const float4*>(Bptr); Bptr += (size_t)BKk * N;
        }
        GEMM_COMPUTE(As[cur], Bs[cur])
        if (has_next) {
            int nxt = cur ^ 1;
            GEMM_STORE_STAGE(nxt, av, bv)
            __syncthreads();
            cur = nxt;
        }
    }
    #pragma unroll
    for (int i = 0; i < 8; i++) {
        int row = m0 + ty * 8 + i;
        float* cp = C + (size_t)row * N + n0 + tx * 8;
        if (resid) {
            const float* rp = resid + (size_t)row * N + n0 + tx * 8;
            #pragma unroll
            for (int j = 0; j < 8; j++) cp[j] = acc[i][j] + rp[j];
        } else {
            #pragma unroll
            for (int j = 0; j < 8; j++) cp[j] = acc[i][j];
        }
    }
}

// ---------------- SGEMM with gathered A rows (expert gate/up) ----------------
__global__ __launch_bounds__(256)
void sgemm_gather_kernel(const float* __restrict__ A, const float* __restrict__ Ball,
                         float* __restrict__ C,
                         const int* __restrict__ cnt, const int* __restrict__ off,
                         const int* __restrict__ tokl, int N, int Kd) {
    int e = blockIdx.z;
    int ecnt = cnt[e], eoff = off[e];
    int m0 = blockIdx.y * BM;
    if (m0 >= ecnt) return;
    const float* B = Ball + (size_t)e * Kd * N;

    __shared__ __align__(16) float As[2][BKk][BM];
    __shared__ __align__(16) float Bs[2][BKk][BN];
    int tid = threadIdx.x;
    int n0 = blockIdx.x * BN;
    int aRow = tid >> 1, aCol = (tid & 1) * 4;
    int bRow = tid >> 5, bCol = (tid & 31) * 4;
    int r = m0 + aRow;
    bool aval = r < ecnt;
    int tok = aval ? tokl[eoff + r] : 0;
    const float* Aptr = A + (size_t)tok * Kd + aCol;
    const float* Bptr = B + (size_t)bRow * N + n0 + bCol;
    int tx = tid & 15, ty = tid >> 4;
    float acc[8][8];
    #pragma unroll
    for (int i = 0; i < 8; i++)
        #pragma unroll
        for (int j = 0; j < 8; j++) acc[i][j] = 0.f;

    {
        float4 av = aval ? *reinterpret_cast<const float4*>(Aptr)
                         : make_float4(0.f, 0.f, 0.f, 0.f);
        Aptr += BKk;
        float4 bv = *reinterpret_cast<const float4*>(Bptr); Bptr += (size_t)BKk * N;
        GEMM_STORE_STAGE(0, av, bv)
    }
    __syncthreads();
    int cur = 0;
    for (int k0 = 0; k0 < Kd; k0 += BKk) {
        bool has_next = (k0 + BKk) < Kd;
        float4 av, bv;
        if (has_next) {
            av = aval ? *reinterpret_cast<const float4*>(Aptr)
                      : make_float4(0.f, 0.f, 0.f, 0.f);
            Aptr += BKk;
            bv = *reinterpret_cast<const float4*>(Bptr); Bptr += (size_t)BKk * N;
        }
        GEMM_COMPUTE(As[cur], Bs[cur])
        if (has_next) {
            int nxt = cur ^ 1;
            GEMM_STORE_STAGE(nxt, av, bv)
            __syncthreads();
            cur = nxt;
        }
    }
    #pragma unroll
    for (int i = 0; i < 8; i++) {
        int rr = m0 + ty * 8 + i;
        if (rr < ecnt) {
            float* cp = C + (size_t)(eoff + rr) * N + n0 + tx * 8;
            #pragma unroll
            for (int j = 0; j < 8; j++) cp[j] = acc[i][j];
        }
    }
}

// ---------------- SGEMM down-proj: gated atomic scatter into moe accumulator ----------------
__global__ __launch_bounds__(256)
void sgemm_down_kernel(const float* __restrict__ A, const float* __restrict__ Ball,
                       float* __restrict__ Cmoe,
                       const int* __restrict__ cnt, const int* __restrict__ off,
                       const int* __restrict__ tokl, const float* __restrict__ gatel,
                       int N, int Kd) {
    int e = blockIdx.z;
    int ecnt = cnt[e], eoff = off[e];
    int m0 = blockIdx.y * BM;
    if (m0 >= ecnt) return;
    const float* B = Ball + (size_t)e * Kd * N;

    __shared__ __align__(16) float As[2][BKk][BM];
    __shared__ __align__(16) float Bs[2][BKk][BN];
    int tid = threadIdx.x;
    int n0 = blockIdx.x * BN;
    int aRow = tid >> 1, aCol = (tid & 1) * 4;
    int bRow = tid >> 5, bCol = (tid & 31) * 4;
    int r = m0 + aRow;
    int slot = (r < ecnt) ? (eoff + r) : 0;
    const float* Aptr = A + (size_t)slot * Kd + aCol;
    const float* Bptr = B + (size_t)bRow * N + n0 + bCol;
    int tx = tid & 15, ty = tid >> 4;
    float acc[8][8];
    #pragma unroll
    for (int i = 0; i < 8; i++)
        #pragma unroll
        for (int j = 0; j < 8; j++) acc[i][j] = 0.f;

    {
        float4 av = *reinterpret_cast<const float4*>(Aptr); Aptr += BKk;
        float4 bv = *reinterpret_cast<const float4*>(Bptr); Bptr += (size_t)BKk * N;
        GEMM_STORE_STAGE(0, av, bv)
    }
    __syncthreads();
    int cur = 0;
    for (int k0 = 0; k0 < Kd; k0 += BKk) {
        bool has_next = (k0 + BKk) < Kd;
        float4 av, bv;
        if (has_next) {
            av = *reinterpret_cast<const float4*>(Aptr); Aptr += BKk;
            bv = *reinterpret_cast<const float4*>(Bptr); Bptr += (size_t)BKk * N;
        }
        GEMM_COMPUTE(As[cur], Bs[cur])
        if (has_next) {
            int nxt = cur ^ 1;
            GEMM_STORE_STAGE(nxt, av, bv)
            __syncthreads();
            cur = nxt;
        }
    }
    #pragma unroll
    for (int i = 0; i < 8; i++) {
        int rr = m0 + ty * 8 + i;
        if (rr < ecnt) {
            int sl = eoff + rr;
            int tok = tokl[sl];
            float ga = gatel[sl];
            float* cp = Cmoe + (size_t)tok * N + n0 + tx * 8;
            #pragma unroll
            for (int j = 0; j < 8; j++) atomicAdd(&cp[j], ga * acc[i][j]);
        }
    }
}

// ---------------- RoPE (in place), pairs (d, d+32) per thread ----------------
__global__ void rope_kernel(float* __restrict__ buf, const float* __restrict__ cosp,
                            const float* __restrict__ sinp, int nheads) {
    int i = blockIdx.x * blockDim.x + threadIdx.x;
    int d = i & 31;
    int rest = i >> 5;
    int hh = rest % nheads;
    int t = rest / nheads;
    if (t >= NTOK) return;
    int s = t & (SEQ - 1);
    size_t base = (size_t)t * (nheads * HDIM) + hh * HDIM;
    float x1 = buf[base + d];
    float x2 = buf[base + d + 32];
    float c = cosp[s * HDIM + d];
    float sn = sinp[s * HDIM + d];
    buf[base + d]      = x1 * c - x2 * sn;
    buf[base + d + 32] = x2 * c + x1 * sn;
}

// ---------------- Flash attention (causal, GQA), 64 queries/block ----------------
__global__ __launch_bounds__(64)
void attn_kernel(const float* __restrict__ q, const float* __restrict__ Kg,
                 const float* __restrict__ Vg, float* __restrict__ o) {
    __shared__ __align__(16) float Ks[32][HDIM];
    __shared__ __align__(16) float Vs[32][HDIM];
    int b = blockIdx.z, h = blockIdx.y, q0 = blockIdx.x * 64;
    int tid = threadIdx.x;
    int kvh = h >> 2;                 // H/KV = 4
    int qi = q0 + tid;
    const float* qp = q + ((size_t)(b * SEQ + qi)) * DMODEL + h * HDIM;
    float qreg[64], oacc[64];
    #pragma unroll
    for (int d = 0; d < 64; d++) { qreg[d] = qp[d] * 0.125f; oacc[d] = 0.f; }
    float m = -1e30f, l = 0.f;

    for (int k0 = 0; k0 < q0 + 64; k0 += 32) {
        __syncthreads();
        for (int i = tid; i < 32 * 16; i += 64) {
            int row = i >> 4, c4 = (i & 15) * 4;
            size_t gidx = ((size_t)((b * SEQ + k0 + row) * NKV + kvh)) * HDIM + c4;
            *reinterpret_cast<float4*>(&Ks[row][c4]) = *reinterpret_cast<const float4*>(&Kg[gidx]);
            *reinterpret_cast<float4*>(&Vs[row][c4]) = *reinterpret_cast<const float4*>(&Vg[gidx]);
        }
        __syncthreads();
        float sreg[32];
        float mt = m;
        #pragma unroll
        for (int j = 0; j < 32; j++) {
            float s;
            if (k0 + j > qi) s = -1e9f;
            else {
                s = 0.f;
                #pragma unroll
                for (int d = 0; d < 64; d++) s += qreg[d] * Ks[j][d];
            }
            sreg[j] = s;
            mt = fmaxf(mt, s);
        }
        float c = __expf(m - mt);
        l *= c;
        #pragma unroll
        for (int d = 0; d < 64; d++) oacc[d] *= c;
        #pragma unroll
        for (int j = 0; j < 32; j++) {
            float p = __expf(sreg[j] - mt);
            l += p;
            #pragma unroll
            for (int d = 0; d < 64; d++) oacc[d] += p * Vs[j][d];
        }
        m = mt;
    }
    float inv = 1.f / l;
    float* op = o + ((size_t)(b * SEQ + qi)) * DMODEL + h * HDIM;
    #pragma unroll
    for (int d = 0; d < 64; d++) op[d] = oacc[d] * inv;
}

// ---------------- Router + top-2 (one warp per token) ----------------
__global__ void router_kernel(const float* __restrict__ yn, const float* __restrict__ rw,
                              int* __restrict__ topk_e, float* __restrict__ topk_w,
                              int* __restrict__ cnt) {
    int gt = blockIdx.x * blockDim.x + threadIdx.x;
    int t = gt >> 5;
    int lane = threadIdx.x & 31;
    if (t >= NTOK) return;
    const float* yr = yn + (size_t)t * DMODEL;
    float acc[NEXP];
    #pragma unroll
    for (int e = 0; e < NEXP; e++) acc[e] = 0.f;
    for (int d = lane; d < DMODEL; d += 32) {
        float x = yr[d];
        #pragma unroll
        for (int e = 0; e < NEXP; e++) acc[e] += x * rw[d * NEXP + e];
    }
    #pragma unroll
    for (int e = 0; e < NEXP; e++)
        for (int o = 16; o; o >>= 1) acc[e] += __shfl_down_sync(0xffffffffu, acc[e], o);
    if (lane == 0) {
        float v1 = -1e30f, v2 = -1e30f; int e1 = 0, e2 = 0;
        #pragma unroll
        for (int e = 0; e < NEXP; e++) {
            float v = acc[e];
            if (v > v1) { v2 = v1; e2 = e1; v1 = v; e1 = e; }
            else if (v > v2) { v2 = v; e2 = e; }
        }
        float e2v = __expf(v2 - v1);
        float den = 1.f + e2v;
        topk_e[t * 2 + 0] = e1; topk_w[t * 2 + 0] = 1.f / den;
        topk_e[t * 2 + 1] = e2; topk_w[t * 2 + 1] = e2v / den;
        atomicAdd(&cnt[e1], 1);
        atomicAdd(&cnt[e2], 1);
    }
}

__global__ void scan_kernel(const int* cnt, int* off, int* cur) {
    if (threadIdx.x == 0 && blockIdx.x == 0) {
        int run = 0;
        for (int e = 0; e < NEXP; e++) { off[e] = run; cur[e] = run; run += cnt[e]; }
    }
}

__global__ void scatter_kernel(const int* __restrict__ topk_e, const float* __restrict__ topk_w,
                               int* __restrict__ cur, int* __restrict__ tokl,
                               float* __restrict__ gatel) {
    int t = blockIdx.x * blockDim.x + threadIdx.x;
    if (t >= NTOK) return;
    #pragma unroll
    for (int j = 0; j < 2; j++) {
        int e = topk_e[t * 2 + j];
        int slot = atomicAdd(&cur[e], 1);
        tokl[slot] = t;
        gatel[slot] = topk_w[t * 2 + j];
    }
}

__global__ void silu_mul_kernel(float* __restrict__ G, const float* __restrict__ U) {
    size_t i = (size_t)blockIdx.x * blockDim.x + threadIdx.x;
    if (i < (size_t)NSLOT * FDIM) {
        float g = G[i];
        G[i] = (g / (1.f + __expf(-g))) * U[i];
    }
}

__global__ void add_kernel(const float* __restrict__ h, const float* __restrict__ moe,
                           float* __restrict__ out) {
    int i = blockIdx.x * blockDim.x + threadIdx.x;
    if (i < NTOK * DMODEL) out[i] = h[i] + moe[i];
}

// ---------------- host launcher ----------------
extern "C" void kernel_launch(void* const* d_in, const int* in_sizes, int n_in,
                              void* d_out, int out_size) {
    const float* x      = (const float*)d_in[0];
    const float* cosp   = (const float*)d_in[1];
    const float* sinp   = (const float*)d_in[2];
    // d_in[3] = mask (unused; causal computed analytically)
    const float* w_attn = (const float*)d_in[4];
    const float* w_moe  = (const float*)d_in[5];
    const float* Wq     = (const float*)d_in[6];
    const float* Wk     = (const float*)d_in[7];
    const float* Wv     = (const float*)d_in[8];
    const float* Wo     = (const float*)d_in[9];
    const float* Wr     = (const float*)d_in[10];
    const float* Wg     = (const float*)d_in[11];
    const float* Wu     = (const float*)d_in[12];
    const float* Wd     = (const float*)d_in[13];

    float* out  = (float*)d_out;
    float* outK = out + (size_t)NTOK * DMODEL;
    float* outV = outK + (size_t)NTOK * NKV * HDIM;

    float *p_xn, *p_q, *p_o, *p_h, *p_yn, *p_moe, *p_heG, *p_heU, *p_tw, *p_gate;
    int *p_te, *p_cnt, *p_off, *p_cur, *p_tok;
    cudaGetSymbolAddress((void**)&p_xn,  g_xn);
    cudaGetSymbolAddress((void**)&p_q,   g_q);
    cudaGetSymbolAddress((void**)&p_o,   g_o);
    cudaGetSymbolAddress((void**)&p_h,   g_h);
    cudaGetSymbolAddress((void**)&p_yn,  g_yn);
    cudaGetSymbolAddress((void**)&p_moe, g_moe);
    cudaGetSymbolAddress((void**)&p_heG, g_heG);
    cudaGetSymbolAddress((void**)&p_heU, g_heU);
    cudaGetSymbolAddress((void**)&p_te,  g_topk_e);
    cudaGetSymbolAddress((void**)&p_tw,  g_topk_w);
    cudaGetSymbolAddress((void**)&p_cnt, g_cnt);
    cudaGetSymbolAddress((void**)&p_off, g_off);
    cudaGetSymbolAddress((void**)&p_cur, g_cur);
    cudaGetSymbolAddress((void**)&p_tok, g_tok);
    cudaGetSymbolAddress((void**)&p_gate,g_gate);

    // 1. zero moe accumulator + counters
    zero_kernel<<<(NTOK*DMODEL + 255)/256, 256>>>(p_moe, p_cnt);
    // 2. attn rmsnorm
    rmsnorm_kernel<<<NTOK, 256>>>(x, w_attn, p_xn);
    // 3. QKV projections (v straight to output, k to output then roped in place)
    sgemm_kernel<<<dim3(DMODEL/BN, NTOK/BM), 256>>>(p_xn, Wq, p_q, NTOK, DMODEL, DMODEL, nullptr);
    sgemm_kernel<<<dim3((NKV*HDIM)/BN, NTOK/BM), 256>>>(p_xn, Wk, outK, NTOK, NKV*HDIM, DMODEL, nullptr);
    sgemm_kernel<<<dim3((NKV*HDIM)/BN, NTOK/BM), 256>>>(p_xn, Wv, outV, NTOK, NKV*HDIM, DMODEL, nullptr);
    // 4. RoPE
    rope_kernel<<<(NTOK*NH*32)/256, 256>>>(p_q, cosp, sinp, NH);
    rope_kernel<<<(NTOK*NKV*32)/256, 256>>>(outK, cosp, sinp, NKV);
    // 5. attention
    attn_kernel<<<dim3(SEQ/64, NH, BATCH), 64>>>(p_q, outK, outV, p_o);
    // 6. output proj + residual
    sgemm_kernel<<<dim3(DMODEL/BN, NTOK/BM), 256>>>(p_o, Wo, p_h, NTOK, DMODEL, DMODEL, x);
    // 7. moe rmsnorm
    rmsnorm_kernel<<<NTOK, 256>>>(p_h, w_moe, p_yn);
    // 8. router + top-2 + grouping
    router_kernel<<<NTOK/4, 128>>>(p_yn, Wr, p_te, p_tw, p_cnt);
    scan_kernel<<<1, 1>>>(p_cnt, p_off, p_cur);
    scatter_kernel<<<NTOK/256, 256>>>(p_te, p_tw, p_cur, p_tok, p_gate);
    // 9. expert gate & up projections (gathered rows), then silu*mul
    sgemm_gather_kernel<<<dim3(FDIM/BN, NSLOT/BM, NEXP), 256>>>(p_yn, Wg, p_heG, p_cnt, p_off, p_tok, FDIM, DMODEL);
    sgemm_gather_kernel<<<dim3(FDIM/BN, NSLOT/BM, NEXP), 256>>>(p_yn, Wu, p_heU, p_cnt, p_off, p_tok, FDIM, DMODEL);
    silu_mul_kernel<<<(unsigned)(((size_t)NSLOT*FDIM + 255)/256), 256>>>(p_heG, p_heU);
    // 10. down projection, gated atomic scatter into moe
    sgemm_down_kernel<<<dim3(DMODEL/BN, NSLOT/BM, NEXP), 256>>>(p_heG, Wd, p_moe, p_cnt, p_off, p_tok, p_gate, DMODEL, FDIM);
    // 11. final residual
    add_kernel<<<(NTOK*DMODEL + 255)/256, 256>>>(p_h, p_moe, out);
}

// round 6
// speedup vs baseline: 1.2271x; 1.2271x over previous
#include <cuda_runtime.h>
#include <cstdint>

#define BATCH  4
#define SEQ    2048
#define DMODEL 1024
#define NH     16
#define NKV    4
#define HDIM   64
#define NEXP   8
#define FDIM   1024
#define NTOK   (BATCH*SEQ)      // 8192
#define NSLOT  (NTOK*2)         // 16384

// ---------------- device scratch (static, allocation-rule safe) ----------------
__device__ float g_xn [NTOK*DMODEL];
__device__ float g_q  [NTOK*DMODEL];
__device__ float g_o  [NTOK*DMODEL];
__device__ float g_h  [NTOK*DMODEL];
__device__ float g_yn [NTOK*DMODEL];
__device__ float g_moe[NTOK*DMODEL];
__device__ float g_heG[(size_t)NSLOT*FDIM];
__device__ float g_heU[(size_t)NSLOT*FDIM];
__device__ int   g_topk_e[NTOK*2];
__device__ float g_topk_w[NTOK*2];
__device__ int   g_cnt[NEXP];
__device__ int   g_off[NEXP];
__device__ int   g_cur[NEXP];
__device__ int   g_tok[NSLOT];
__device__ float g_gate[NSLOT];

// ---------------- small helpers ----------------
__device__ __forceinline__ uint32_t f2tf32(float x) {
    uint32_t r;
    asm("cvt.rna.tf32.f32 %0, %1;" : "=r"(r) : "f"(x));
    return r;
}

__device__ __forceinline__ void mma_tf32(float* d, const uint32_t* a, const uint32_t* b) {
    asm volatile(
        "mma.sync.aligned.m16n8k8.row.col.f32.tf32.tf32.f32 "
        "{%0,%1,%2,%3}, {%4,%5,%6,%7}, {%8,%9}, {%0,%1,%2,%3};\n"
        : "+f"(d[0]), "+f"(d[1]), "+f"(d[2]), "+f"(d[3])
        : "r"(a[0]), "r"(a[1]), "r"(a[2]), "r"(a[3]), "r"(b[0]), "r"(b[1]));
}

// ---------------- zero moe accumulator + expert counters ----------------
__global__ void zero_kernel(float* moe, int* cnt) {
    int i = blockIdx.x * blockDim.x + threadIdx.x;
    if (i < NTOK*DMODEL) moe[i] = 0.f;
    if (i < NEXP) cnt[i] = 0;
}

// ---------------- RMSNorm: one block per row ----------------
__global__ void rmsnorm_kernel(const float* __restrict__ x, const float* __restrict__ w,
                               float* __restrict__ out) {
    int row = blockIdx.x;
    const float* xr = x + (size_t)row * DMODEL;
    float ss = 0.f;
    for (int d = threadIdx.x; d < DMODEL; d += 256) { float v = xr[d]; ss += v * v; }
    __shared__ float red[8];
    for (int o = 16; o; o >>= 1) ss += __shfl_down_sync(0xffffffffu, ss, o);
    if ((threadIdx.x & 31) == 0) red[threadIdx.x >> 5] = ss;
    __syncthreads();
    if (threadIdx.x < 8) {
        float v = red[threadIdx.x];
        for (int o = 4; o; o >>= 1) v += __shfl_down_sync(0xffu, v, o);
        if (threadIdx.x == 0) red[0] = v;
    }
    __syncthreads();
    float rs = rsqrtf(red[0] / (float)DMODEL + 1e-6f);
    for (int d = threadIdx.x; d < DMODEL; d += 256)
        out[(size_t)row * DMODEL + d] = xr[d] * rs * w[d];
}

// ============================================================================
// fp32 SIMT SGEMM (kept ONLY for Wk/Wv so that k,v outputs stay fp32-exact)
// ============================================================================
#define BM 128
#define BN 128
#define BKk 8

#define GEMM_COMPUTE(AsS, BsS)                                              \
    _Pragma("unroll")                                                       \
    for (int k = 0; k < BKk; ++k) {                                         \
        float4 a0 = *reinterpret_cast<const float4*>(&AsS[k][ty * 8]);      \
        float4 a1 = *reinterpret_cast<const float4*>(&AsS[k][ty * 8 + 4]);  \
        float4 b0 = *reinterpret_cast<const float4*>(&BsS[k][tx * 8]);      \
        float4 b1 = *reinterpret_cast<const float4*>(&BsS[k][tx * 8 + 4]);  \
        float a[8] = {a0.x,a0.y,a0.z,a0.w,a1.x,a1.y,a1.z,a1.w};             \
        float b[8] = {b0.x,b0.y,b0.z,b0.w,b1.x,b1.y,b1.z,b1.w};             \
        _Pragma("unroll")                                                   \
        for (int i = 0; i < 8; i++)                                         \
            _Pragma("unroll")                                               \
            for (int j = 0; j < 8; j++) acc[i][j] += a[i] * b[j];           \
    }

#define GEMM_STORE_STAGE(st, av, bv)                                        \
    As[st][aCol + 0][aRow] = av.x; As[st][aCol + 1][aRow] = av.y;           \
    As[st][aCol + 2][aRow] = av.z; As[st][aCol + 3][aRow] = av.w;           \
    *reinterpret_cast<float4*>(&Bs[st][bRow][bCol]) = bv;

__global__ __launch_bounds__(256)
void sgemm_kernel(const float* __restrict__ A, const float* __restrict__ B,
                  float* __restrict__ C, int M, int N, int Kd,
                  const float* __restrict__ resid) {
    __shared__ __align__(16) float As[2][BKk][BM];
    __shared__ __align__(16) float Bs[2][BKk][BN];
    int tid = threadIdx.x;
    int m0 = blockIdx.y * BM, n0 = blockIdx.x * BN;
    int aRow = tid >> 1, aCol = (tid & 1) * 4;
    int bRow = tid >> 5, bCol = (tid & 31) * 4;
    const float* Aptr = A + (size_t)(m0 + aRow) * Kd + aCol;
    const float* Bptr = B + (size_t)bRow * N + n0 + bCol;
    int tx = tid & 15, ty = tid >> 4;
    float acc[8][8];
    #pragma unroll
    for (int i = 0; i < 8; i++)
        #pragma unroll
        for (int j = 0; j < 8; j++) acc[i][j] = 0.f;

    {
        float4 av = *reinterpret_cast<const float4*>(Aptr); Aptr += BKk;
        float4 bv = *reinterpret_cast<const float4*>(Bptr); Bptr += (size_t)BKk * N;
        GEMM_STORE_STAGE(0, av, bv)
    }
    __syncthreads();
    int cur = 0;
    for (int k0 = 0; k0 < Kd; k0 += BKk) {
        bool has_next = (k0 + BKk) < Kd;
        float4 av, bv;
        if (has_next) {
            av = *reinterpret_cast<const float4*>(Aptr); Aptr += BKk;
            bv = *reinterpret_cast<const float4*>(Bptr); Bptr += (size_t)BKk * N;
        }
        GEMM_COMPUTE(As[cur], Bs[cur])
        if (has_next) {
            int nxt = cur ^ 1;
            GEMM_STORE_STAGE(nxt, av, bv)
            __syncthreads();
            cur = nxt;
        }
    }
    #pragma unroll
    for (int i = 0; i < 8; i++) {
        int row = m0 + ty * 8 + i;
        float* cp = C + (size_t)row * N + n0 + tx * 8;
        if (resid) {
            const float* rp = resid + (size_t)row * N + n0 + tx * 8;
            #pragma unroll
            for (int j = 0; j < 8; j++) cp[j] = acc[i][j] + rp[j];
        } else {
            #pragma unroll
            for (int j = 0; j < 8; j++) cp[j] = acc[i][j];
        }
    }
}

// ============================================================================
// tf32 tensor-core GEMM: 128x128x16 tile, 8 warps (4x2), warp tile 32x64,
// mma.sync.m16n8k8, fragments pre-packed in smem (conflict-free LDS.128/64).
// MODE 0: C = A*B (+resid)    MODE 1: gathered A rows (expert gate/up)
// MODE 2: contiguous A slots, gated atomicAdd scatter into Cmoe (down proj)
// ============================================================================

#define TG_LOAD_REGS(ktv)                                                        \
    {                                                                            \
        if (MODE == 1 && !avalid) {                                              \
            _Pragma("unroll") for (int c = 0; c < 8; c++) aBuf[c] = 0.f;         \
        } else {                                                                 \
            float4 t0 = *reinterpret_cast<const float4*>(Arow + (ktv) * 16);     \
            float4 t1 = *reinterpret_cast<const float4*>(Arow + (ktv) * 16 + 4); \
            aBuf[0]=t0.x; aBuf[1]=t0.y; aBuf[2]=t0.z; aBuf[3]=t0.w;              \
            aBuf[4]=t1.x; aBuf[5]=t1.y; aBuf[6]=t1.z; aBuf[7]=t1.w;              \
        }                                                                        \
        {                                                                        \
            const float* bp = Brow + (size_t)(ktv) * 16 * N;                     \
            float4 t0 = *reinterpret_cast<const float4*>(bp);                    \
            float4 t1 = *reinterpret_cast<const float4*>(bp + 4);                \
            bBuf[0]=t0.x; bBuf[1]=t0.y; bBuf[2]=t0.z; bBuf[3]=t0.w;              \
            bBuf[4]=t1.x; bBuf[5]=t1.y; bBuf[6]=t1.z; bBuf[7]=t1.w;              \
        }                                                                        \
    }

#define TG_STS_TILE(st)                                                          \
    {                                                                            \
        _Pragma("unroll") for (int c = 0; c < 8; c++)                            \
            AsF[st][a_sts[c]] = f2tf32(aBuf[c]);                                 \
        _Pragma("unroll") for (int c = 0; c < 8; c++)                            \
            BsF[st][b_sts[c]] = f2tf32(bBuf[c]);                                 \
    }

template<int MODE>
__global__ __launch_bounds__(256)
void tgemm_kernel(const float* __restrict__ A, const float* __restrict__ Ball,
                  float* __restrict__ C, const float* __restrict__ resid,
                  const int* __restrict__ cnt, const int* __restrict__ off,
                  const int* __restrict__ tokl, const float* __restrict__ gatel,
                  int N, int Kd, int M)
{
    int ecnt = M, eoff = 0;
    const float* B = Ball;
    if (MODE != 0) {
        int e = blockIdx.z;
        ecnt = cnt[e]; eoff = off[e];
        B = Ball + (size_t)e * Kd * N;
        if ((int)(blockIdx.y * 128) >= ecnt) return;
    }
    const int tid = threadIdx.x;
    const int m0 = blockIdx.y * 128;
    const int n0 = blockIdx.x * 128;

    __shared__ uint32_t AsF[2][2048];   // frag-packed A tile (128x16 tf32)
    __shared__ uint32_t BsF[2][2048];   // frag-packed B tile (16x128 tf32)

    // ---- loader: A row per thread-pair, 8 floats each ----
    const int lm = tid >> 1;            // local m row 0..127
    const int lk = (tid & 1) * 8;       // k offset within BK=16
    bool avalid = true;
    int arow;
    if (MODE == 0)      arow = m0 + lm;
    else if (MODE == 1) { avalid = (m0 + lm) < ecnt; arow = avalid ? tokl[eoff + m0 + lm] : 0; }
    else                { avalid = (m0 + lm) < ecnt; arow = avalid ? (eoff + m0 + lm) : eoff; }
    const float* Arow = A + (size_t)arow * Kd + lk;

    const int bk = tid >> 4;            // B k-row 0..15
    const int bn = (tid & 15) * 8;      // 8 floats along n
    const float* Brow = B + (size_t)bk * N + n0 + bn;

    // frag-scatter addresses (element index into 2048-word tile)
    uint32_t a_sts[8];
    {
        int im = lm >> 4, r = lm & 15;
        #pragma unroll
        for (int c = 0; c < 8; c++) {
            int k = lk + c, ik = k >> 3, cc = k & 7;
            a_sts[c] = ((im * 2 + ik) * 32 + (r & 7) * 4 + (cc & 3)) * 4
                     + (r >> 3) + 2 * (cc >> 2);
        }
    }
    uint32_t b_sts[8];
    {
        int kk = bk & 7, ik = bk >> 3;
        #pragma unroll
        for (int c = 0; c < 8; c++) {
            int n = bn + c, in8 = n >> 3, nn = n & 7;
            b_sts[c] = ((in8 * 2 + ik) * 32 + nn * 4 + (kk & 3)) * 2 + (kk >> 2);
        }
    }

    // ---- warp layout ----
    const int wid = tid >> 5, lane = tid & 31;
    const int wm = wid & 3, wn = wid >> 2;   // 4 x 2 warps
    const int im0 = wm * 2;                  // 2 m16 frags
    const int in0 = wn * 8;                  // 8 n8 frags

    float acc[2][8][4];
    #pragma unroll
    for (int i = 0; i < 2; i++)
        #pragma unroll
        for (int j = 0; j < 8; j++)
            #pragma unroll
            for (int p = 0; p < 4; p++) acc[i][j][p] = 0.f;

    const int NT = Kd >> 4;
    float aBuf[8], bBuf[8];

    TG_LOAD_REGS(0)
    TG_STS_TILE(0)
    __syncthreads();
    int cur = 0;
    for (int kt = 0; kt < NT; kt++) {
        bool hn = (kt + 1) < NT;
        if (hn) TG_LOAD_REGS(kt + 1)
        #pragma unroll
        for (int ik = 0; ik < 2; ik++) {
            uint32_t afrag[2][4], bfrag[8][2];
            #pragma unroll
            for (int i = 0; i < 2; i++) {
                uint4 v = *reinterpret_cast<const uint4*>(
                    &AsF[cur][(((im0 + i) * 2 + ik) * 32 + lane) * 4]);
                afrag[i][0] = v.x; afrag[i][1] = v.y; afrag[i][2] = v.z; afrag[i][3] = v.w;
            }
            #pragma unroll
            for (int j = 0; j < 8; j++) {
                uint2 v = *reinterpret_cast<const uint2*>(
                    &BsF[cur][(((in0 + j) * 2 + ik) * 32 + lane) * 2]);
                bfrag[j][0] = v.x; bfrag[j][1] = v.y;
            }
            #pragma unroll
            for (int i = 0; i < 2; i++)
                #pragma unroll
                for (int j = 0; j < 8; j++)
                    mma_tf32(acc[i][j], afrag[i], bfrag[j]);
        }
        if (hn) {
            int nxt = cur ^ 1;
            TG_STS_TILE(nxt)
            __syncthreads();
            cur = nxt;
        }
    }

    // ---- epilogue ----
    const int cbase = n0 + wn * 64;
    #pragma unroll
    for (int i = 0; i < 2; i++) {
        #pragma unroll
        for (int h = 0; h < 2; h++) {
            int lr = wm * 32 + i * 16 + h * 8 + (lane >> 2);   // local row in tile
            if (MODE == 0) {
                size_t base = (size_t)(m0 + lr) * N;
                #pragma unroll
                for (int j = 0; j < 8; j++) {
                    int col = cbase + j * 8 + (lane & 3) * 2;
                    float v0 = acc[i][j][h * 2], v1 = acc[i][j][h * 2 + 1];
                    if (resid) {
                        float2 rv = *reinterpret_cast<const float2*>(&resid[base + col]);
                        v0 += rv.x; v1 += rv.y;
                    }
                    *reinterpret_cast<float2*>(&C[base + col]) = make_float2(v0, v1);
                }
            } else if (MODE == 1) {
                if (m0 + lr < ecnt) {
                    size_t base = (size_t)(eoff + m0 + lr) * N;
                    #pragma unroll
                    for (int j = 0; j < 8; j++) {
                        int col = cbase + j * 8 + (lane & 3) * 2;
                        *reinterpret_cast<float2*>(&C[base + col]) =
                            make_float2(acc[i][j][h * 2], acc[i][j][h * 2 + 1]);
                    }
                }
            } else {
                if (m0 + lr < ecnt) {
                    int sl = eoff + m0 + lr;
                    int tok = tokl[sl];
                    float ga = gatel[sl];
                    size_t base = (size_t)tok * N;
                    #pragma unroll
                    for (int j = 0; j < 8; j++) {
                        int col = cbase + j * 8 + (lane & 3) * 2;
                        atomicAdd(&C[base + col],     ga * acc[i][j][h * 2]);
                        atomicAdd(&C[base + col + 1], ga * acc[i][j][h * 2 + 1]);
                    }
                }
            }
        }
    }
}

// ---------------- RoPE (in place), pairs (d, d+32) per thread ----------------
__global__ void rope_kernel(float* __restrict__ buf, const float* __restrict__ cosp,
                            const float* __restrict__ sinp, int nheads) {
    int i = blockIdx.x * blockDim.x + threadIdx.x;
    int d = i & 31;
    int rest = i >> 5;
    int hh = rest % nheads;
    int t = rest / nheads;
    if (t >= NTOK) return;
    int s = t & (SEQ - 1);
    size_t base = (size_t)t * (nheads * HDIM) + hh * HDIM;
    float x1 = buf[base + d];
    float x2 = buf[base + d + 32];
    float c = cosp[s * HDIM + d];
    float sn = sinp[s * HDIM + d];
    buf[base + d]      = x1 * c - x2 * sn;
    buf[base + d + 32] = x2 * c + x1 * sn;
}

// ---------------- Flash attention (causal, GQA), 64 queries/block ----------------
__global__ __launch_bounds__(64)
void attn_kernel(const float* __restrict__ q, const float* __restrict__ Kg,
                 const float* __restrict__ Vg, float* __restrict__ o) {
    __shared__ __align__(16) float Ks[32][HDIM];
    __shared__ __align__(16) float Vs[32][HDIM];
    int b = blockIdx.z, h = blockIdx.y, q0 = blockIdx.x * 64;
    int tid = threadIdx.x;
    int kvh = h >> 2;                 // H/KV = 4
    int qi = q0 + tid;
    const float* qp = q + ((size_t)(b * SEQ + qi)) * DMODEL + h * HDIM;
    float qreg[64], oacc[64];
    #pragma unroll
    for (int d = 0; d < 64; d++) { qreg[d] = qp[d] * 0.125f; oacc[d] = 0.f; }
    float m = -1e30f, l = 0.f;

    for (int k0 = 0; k0 < q0 + 64; k0 += 32) {
        __syncthreads();
        for (int i = tid; i < 32 * 16; i += 64) {
            int row = i >> 4, c4 = (i & 15) * 4;
            size_t gidx = ((size_t)((b * SEQ + k0 + row) * NKV + kvh)) * HDIM + c4;
            *reinterpret_cast<float4*>(&Ks[row][c4]) = *reinterpret_cast<const float4*>(&Kg[gidx]);
            *reinterpret_cast<float4*>(&Vs[row][c4]) = *reinterpret_cast<const float4*>(&Vg[gidx]);
        }
        __syncthreads();
        float sreg[32];
        float mt = m;
        #pragma unroll
        for (int j = 0; j < 32; j++) {
            float s;
            if (k0 + j > qi) s = -1e9f;
            else {
                s = 0.f;
                #pragma unroll
                for (int d = 0; d < 64; d++) s += qreg[d] * Ks[j][d];
            }
            sreg[j] = s;
            mt = fmaxf(mt, s);
        }
        float c = __expf(m - mt);
        l *= c;
        #pragma unroll
        for (int d = 0; d < 64; d++) oacc[d] *= c;
        #pragma unroll
        for (int j = 0; j < 32; j++) {
            float p = __expf(sreg[j] - mt);
            l += p;
            #pragma unroll
            for (int d = 0; d < 64; d++) oacc[d] += p * Vs[j][d];
        }
        m = mt;
    }
    float inv = 1.f / l;
    float* op = o + ((size_t)(b * SEQ + qi)) * DMODEL + h * HDIM;
    #pragma unroll
    for (int d = 0; d < 64; d++) op[d] = oacc[d] * inv;
}

// ---------------- Router + top-2 (one warp per token) ----------------
__global__ void router_kernel(const float* __restrict__ yn, const float* __restrict__ rw,
                              int* __restrict__ topk_e, float* __restrict__ topk_w,
                              int* __restrict__ cnt) {
    int gt = blockIdx.x * blockDim.x + threadIdx.x;
    int t = gt >> 5;
    int lane = threadIdx.x & 31;
    if (t >= NTOK) return;
    const float* yr = yn + (size_t)t * DMODEL;
    float acc[NEXP];
    #pragma unroll
    for (int e = 0; e < NEXP; e++) acc[e] = 0.f;
    for (int d = lane; d < DMODEL; d += 32) {
        float x = yr[d];
        #pragma unroll
        for (int e = 0; e < NEXP; e++) acc[e] += x * rw[d * NEXP + e];
    }
    #pragma unroll
    for (int e = 0; e < NEXP; e++)
        for (int o = 16; o; o >>= 1) acc[e] += __shfl_down_sync(0xffffffffu, acc[e], o);
    if (lane == 0) {
        float v1 = -1e30f, v2 = -1e30f; int e1 = 0, e2 = 0;
        #pragma unroll
        for (int e = 0; e < NEXP; e++) {
            float v = acc[e];
            if (v > v1) { v2 = v1; e2 = e1; v1 = v; e1 = e; }
            else if (v > v2) { v2 = v; e2 = e; }
        }
        float e2v = __expf(v2 - v1);
        float den = 1.f + e2v;
        topk_e[t * 2 + 0] = e1; topk_w[t * 2 + 0] = 1.f / den;
        topk_e[t * 2 + 1] = e2; topk_w[t * 2 + 1] = e2v / den;
        atomicAdd(&cnt[e1], 1);
        atomicAdd(&cnt[e2], 1);
    }
}

__global__ void scan_kernel(const int* cnt, int* off, int* cur) {
    if (threadIdx.x == 0 && blockIdx.x == 0) {
        int run = 0;
        for (int e = 0; e < NEXP; e++) { off[e] = run; cur[e] = run; run += cnt[e]; }
    }
}

__global__ void scatter_kernel(const int* __restrict__ topk_e, const float* __restrict__ topk_w,
                               int* __restrict__ cur, int* __restrict__ tokl,
                               float* __restrict__ gatel) {
    int t = blockIdx.x * blockDim.x + threadIdx.x;
    if (t >= NTOK) return;
    #pragma unroll
    for (int j = 0; j < 2; j++) {
        int e = topk_e[t * 2 + j];
        int slot = atomicAdd(&cur[e], 1);
        tokl[slot] = t;
        gatel[slot] = topk_w[t * 2 + j];
    }
}

__global__ void silu_mul_kernel(float* __restrict__ G, const float* __restrict__ U) {
    size_t i = (size_t)blockIdx.x * blockDim.x + threadIdx.x;
    if (i < (size_t)NSLOT * FDIM) {
        float g = G[i];
        G[i] = (g / (1.f + __expf(-g))) * U[i];
    }
}

__global__ void add_kernel(const float* __restrict__ h, const float* __restrict__ moe,
                           float* __restrict__ out) {
    int i = blockIdx.x * blockDim.x + threadIdx.x;
    if (i < NTOK * DMODEL) out[i] = h[i] + moe[i];
}

// ---------------- host launcher ----------------
extern "C" void kernel_launch(void* const* d_in, const int* in_sizes, int n_in,
                              void* d_out, int out_size) {
    const float* x      = (const float*)d_in[0];
    const float* cosp   = (const float*)d_in[1];
    const float* sinp   = (const float*)d_in[2];
    // d_in[3] = mask (unused; causal computed analytically)
    const float* w_attn = (const float*)d_in[4];
    const float* w_moe  = (const float*)d_in[5];
    const float* Wq     = (const float*)d_in[6];
    const float* Wk     = (const float*)d_in[7];
    const float* Wv     = (const float*)d_in[8];
    const float* Wo     = (const float*)d_in[9];
    const float* Wr     = (const float*)d_in[10];
    const float* Wg     = (const float*)d_in[11];
    const float* Wu     = (const float*)d_in[12];
    const float* Wd     = (const float*)d_in[13];

    float* out  = (float*)d_out;
    float* outK = out + (size_t)NTOK * DMODEL;
    float* outV = outK + (size_t)NTOK * NKV * HDIM;

    float *p_xn, *p_q, *p_o, *p_h, *p_yn, *p_moe, *p_heG, *p_heU, *p_tw, *p_gate;
    int *p_te, *p_cnt, *p_off, *p_cur, *p_tok;
    cudaGetSymbolAddress((void**)&p_xn,  g_xn);
    cudaGetSymbolAddress((void**)&p_q,   g_q);
    cudaGetSymbolAddress((void**)&p_o,   g_o);
    cudaGetSymbolAddress((void**)&p_h,   g_h);
    cudaGetSymbolAddress((void**)&p_yn,  g_yn);
    cudaGetSymbolAddress((void**)&p_moe, g_moe);
    cudaGetSymbolAddress((void**)&p_heG, g_heG);
    cudaGetSymbolAddress((void**)&p_heU, g_heU);
    cudaGetSymbolAddress((void**)&p_te,  g_topk_e);
    cudaGetSymbolAddress((void**)&p_tw,  g_topk_w);
    cudaGetSymbolAddress((void**)&p_cnt, g_cnt);
    cudaGetSymbolAddress((void**)&p_off, g_off);
    cudaGetSymbolAddress((void**)&p_cur, g_cur);
    cudaGetSymbolAddress((void**)&p_tok, g_tok);
    cudaGetSymbolAddress((void**)&p_gate,g_gate);

    // 1. zero moe accumulator + counters
    zero_kernel<<<(NTOK*DMODEL + 255)/256, 256>>>(p_moe, p_cnt);
    // 2. attn rmsnorm
    rmsnorm_kernel<<<NTOK, 256>>>(x, w_attn, p_xn);
    // 3. QKV projections: Q via tf32 tensor cores (feeds attention only);
    //    K/V via fp32 SIMT (they are direct outputs — keep exact)
    tgemm_kernel<0><<<dim3(DMODEL/128, NTOK/128), 256>>>(p_xn, Wq, p_q, nullptr,
        nullptr, nullptr, nullptr, nullptr, DMODEL, DMODEL, NTOK);
    sgemm_kernel<<<dim3((NKV*HDIM)/BN, NTOK/BM), 256>>>(p_xn, Wk, outK, NTOK, NKV*HDIM, DMODEL, nullptr);
    sgemm_kernel<<<dim3((NKV*HDIM)/BN, NTOK/BM), 256>>>(p_xn, Wv, outV, NTOK, NKV*HDIM, DMODEL, nullptr);
    // 4. RoPE
    rope_kernel<<<(NTOK*NH*32)/256, 256>>>(p_q, cosp, sinp, NH);
    rope_kernel<<<(NTOK*NKV*32)/256, 256>>>(outK, cosp, sinp, NKV);
    // 5. attention
    attn_kernel<<<dim3(SEQ/64, NH, BATCH), 64>>>(p_q, outK, outV, p_o);
    // 6. output proj + residual (tf32)
    tgemm_kernel<0><<<dim3(DMODEL/128, NTOK/128), 256>>>(p_o, Wo, p_h, x,
        nullptr, nullptr, nullptr, nullptr, DMODEL, DMODEL, NTOK);
    // 7. moe rmsnorm
    rmsnorm_kernel<<<NTOK, 256>>>(p_h, w_moe, p_yn);
    // 8. router + top-2 + grouping
    router_kernel<<<NTOK/4, 128>>>(p_yn, Wr, p_te, p_tw, p_cnt);
    scan_kernel<<<1, 1>>>(p_cnt, p_off, p_cur);
    scatter_kernel<<<NTOK/256, 256>>>(p_te, p_tw, p_cur, p_tok, p_gate);
    // 9. expert gate & up projections (tf32, gathered rows), then silu*mul
    tgemm_kernel<1><<<dim3(FDIM/128, NSLOT/128, NEXP), 256>>>(p_yn, Wg, p_heG, nullptr,
        p_cnt, p_off, p_tok, nullptr, FDIM, DMODEL, 0);
    tgemm_kernel<1><<<dim3(FDIM/128, NSLOT/128, NEXP), 256>>>(p_yn, Wu, p_heU, nullptr,
        p_cnt, p_off, p_tok, nullptr, FDIM, DMODEL, 0);
    silu_mul_kernel<<<(unsigned)(((size_t)NSLOT*FDIM + 255)/256), 256>>>(p_heG, p_heU);
    // 10. down projection (tf32), gated atomic scatter into moe
    tgemm_kernel<2><<<dim3(DMODEL/128, NSLOT/128, NEXP), 256>>>(p_heG, Wd, p_moe, nullptr,
        p_cnt, p_off, p_tok, p_gate, DMODEL, FDIM, 0);
    // 11. final residual
    add_kernel<<<(NTOK*DMODEL + 255)/256, 256>>>(p_h, p_moe, out);
}

// round 10
// speedup vs baseline: 1.8417x; 1.5009x over previous
#include <cuda_runtime.h>
#include <cstdint>

#define BATCH  4
#define SEQ    2048
#define DMODEL 1024
#define NH     16
#define NKV    4
#define HDIM   64
#define NEXP   8
#define FDIM   1024
#define NTOK   (BATCH*SEQ)      // 8192
#define NSLOT  (NTOK*2)         // 16384

// ---------------- device scratch (static, allocation-rule safe) ----------------
__device__ float g_xn [NTOK*DMODEL];
__device__ float g_q  [NTOK*DMODEL];
__device__ float g_o  [NTOK*DMODEL];
__device__ float g_h  [NTOK*DMODEL];
__device__ float g_yn [NTOK*DMODEL];
__device__ float g_moe[NTOK*DMODEL];
__device__ float g_heG[(size_t)NSLOT*FDIM];
__device__ float g_heU[(size_t)NSLOT*FDIM];
__device__ int   g_topk_e[NTOK*2];
__device__ float g_topk_w[NTOK*2];
__device__ int   g_cnt[NEXP];
__device__ int   g_off[NEXP];
__device__ int   g_cur[NEXP];
__device__ int   g_tok[NSLOT];
__device__ float g_gate[NSLOT];

// ---------------- small helpers ----------------
__device__ __forceinline__ uint32_t f2tf32(float x) {
    uint32_t r;
    asm("cvt.rna.tf32.f32 %0, %1;" : "=r"(r) : "f"(x));
    return r;
}

__device__ __forceinline__ void mma_tf32(float* d, const uint32_t* a, const uint32_t* b) {
    asm volatile(
        "mma.sync.aligned.m16n8k8.row.col.f32.tf32.tf32.f32 "
        "{%0,%1,%2,%3}, {%4,%5,%6,%7}, {%8,%9}, {%0,%1,%2,%3};\n"
        : "+f"(d[0]), "+f"(d[1]), "+f"(d[2]), "+f"(d[3])
        : "r"(a[0]), "r"(a[1]), "r"(a[2]), "r"(a[3]), "r"(b[0]), "r"(b[1]));
}

// ---------------- zero moe accumulator + expert counters ----------------
__global__ void zero_kernel(float* moe, int* cnt) {
    int i = blockIdx.x * blockDim.x + threadIdx.x;
    if (i < NTOK*DMODEL) moe[i] = 0.f;
    if (i < NEXP) cnt[i] = 0;
}

// ---------------- RMSNorm: one block per row ----------------
__global__ void rmsnorm_kernel(const float* __restrict__ x, const float* __restrict__ w,
                               float* __restrict__ out) {
    int row = blockIdx.x;
    const float* xr = x + (size_t)row * DMODEL;
    float ss = 0.f;
    for (int d = threadIdx.x; d < DMODEL; d += 256) { float v = xr[d]; ss += v * v; }
    __shared__ float red[8];
    for (int o = 16; o; o >>= 1) ss += __shfl_down_sync(0xffffffffu, ss, o);
    if ((threadIdx.x & 31) == 0) red[threadIdx.x >> 5] = ss;
    __syncthreads();
    if (threadIdx.x < 8) {
        float v = red[threadIdx.x];
        for (int o = 4; o; o >>= 1) v += __shfl_down_sync(0xffu, v, o);
        if (threadIdx.x == 0) red[0] = v;
    }
    __syncthreads();
    float rs = rsqrtf(red[0] / (float)DMODEL + 1e-6f);
    for (int d = threadIdx.x; d < DMODEL; d += 256)
        out[(size_t)row * DMODEL + d] = xr[d] * rs * w[d];
}

// ============================================================================
// tf32 tensor-core GEMM: 128x128x16 tile, 8 warps (4x2), warp tile 32x64,
// mma.sync.m16n8k8, fragments pre-packed in smem (conflict-free LDS.128/64).
// MODE 0: C = A*B (+resid)    MODE 1: gathered A rows (expert gate/up)
// MODE 2: contiguous A slots, gated atomicAdd scatter into Cmoe (down proj)
// ============================================================================

#define TG_LOAD_REGS(ktv)                                                        \
    {                                                                            \
        if (MODE == 1 && !avalid) {                                              \
            _Pragma("unroll") for (int c = 0; c < 8; c++) aBuf[c] = 0.f;         \
        } else {                                                                 \
            float4 t0 = *reinterpret_cast<const float4*>(Arow + (ktv) * 16);     \
            float4 t1 = *reinterpret_cast<const float4*>(Arow + (ktv) * 16 + 4); \
            aBuf[0]=t0.x; aBuf[1]=t0.y; aBuf[2]=t0.z; aBuf[3]=t0.w;              \
            aBuf[4]=t1.x; aBuf[5]=t1.y; aBuf[6]=t1.z; aBuf[7]=t1.w;              \
        }                                                                        \
        {                                                                        \
            const float* bp = Brow + (size_t)(ktv) * 16 * N;                     \
            float4 t0 = *reinterpret_cast<const float4*>(bp);                    \
            float4 t1 = *reinterpret_cast<const float4*>(bp + 4);                \
            bBuf[0]=t0.x; bBuf[1]=t0.y; bBuf[2]=t0.z; bBuf[3]=t0.w;              \
            bBuf[4]=t1.x; bBuf[5]=t1.y; bBuf[6]=t1.z; bBuf[7]=t1.w;              \
        }                                                                        \
    }

#define TG_STS_TILE(st)                                                          \
    {                                                                            \
        _Pragma("unroll") for (int c = 0; c < 8; c++)                            \
            AsF[st][a_sts[c]] = f2tf32(aBuf[c]);                                 \
        _Pragma("unroll") for (int c = 0; c < 8; c++)                            \
            BsF[st][b_sts[c]] = f2tf32(bBuf[c]);                                 \
    }

template<int MODE>
__global__ __launch_bounds__(256)
void tgemm_kernel(const float* __restrict__ A, const float* __restrict__ Ball,
                  float* __restrict__ C, const float* __restrict__ resid,
                  const int* __restrict__ cnt, const int* __restrict__ off,
                  const int* __restrict__ tokl, const float* __restrict__ gatel,
                  int N, int Kd, int M)
{
    int ecnt = M, eoff = 0;
    const float* B = Ball;
    if (MODE != 0) {
        int e = blockIdx.z;
        ecnt = cnt[e]; eoff = off[e];
        B = Ball + (size_t)e * Kd * N;
        if ((int)(blockIdx.y * 128) >= ecnt) return;
    }
    const int tid = threadIdx.x;
    const int m0 = blockIdx.y * 128;
    const int n0 = blockIdx.x * 128;

    __shared__ uint32_t AsF[2][2048];   // frag-packed A tile (128x16 tf32)
    __shared__ uint32_t BsF[2][2048];   // frag-packed B tile (16x128 tf32)

    // ---- loader: A row per thread-pair, 8 floats each ----
    const int lm = tid >> 1;            // local m row 0..127
    const int lk = (tid & 1) * 8;       // k offset within BK=16
    bool avalid = true;
    int arow;
    if (MODE == 0)      arow = m0 + lm;
    else if (MODE == 1) { avalid = (m0 + lm) < ecnt; arow = avalid ? tokl[eoff + m0 + lm] : 0; }
    else                { avalid = (m0 + lm) < ecnt; arow = avalid ? (eoff + m0 + lm) : eoff; }
    const float* Arow = A + (size_t)arow * Kd + lk;

    const int bk = tid >> 4;            // B k-row 0..15
    const int bn = (tid & 15) * 8;      // 8 floats along n
    const float* Brow = B + (size_t)bk * N + n0 + bn;

    // frag-scatter addresses (element index into 2048-word tile)
    uint32_t a_sts[8];
    {
        int im = lm >> 4, r = lm & 15;
        #pragma unroll
        for (int c = 0; c < 8; c++) {
            int k = lk + c, ik = k >> 3, cc = k & 7;
            a_sts[c] = ((im * 2 + ik) * 32 + (r & 7) * 4 + (cc & 3)) * 4
                     + (r >> 3) + 2 * (cc >> 2);
        }
    }
    uint32_t b_sts[8];
    {
        int kk = bk & 7, ik = bk >> 3;
        #pragma unroll
        for (int c = 0; c < 8; c++) {
            int n = bn + c, in8 = n >> 3, nn = n & 7;
            b_sts[c] = ((in8 * 2 + ik) * 32 + nn * 4 + (kk & 3)) * 2 + (kk >> 2);
        }
    }

    // ---- warp layout ----
    const int wid = tid >> 5, lane = tid & 31;
    const int wm = wid & 3, wn = wid >> 2;   // 4 x 2 warps
    const int im0 = wm * 2;                  // 2 m16 frags
    const int in0 = wn * 8;                  // 8 n8 frags

    float acc[2][8][4];
    #pragma unroll
    for (int i = 0; i < 2; i++)
        #pragma unroll
        for (int j = 0; j < 8; j++)
            #pragma unroll
            for (int p = 0; p < 4; p++) acc[i][j][p] = 0.f;

    const int NT = Kd >> 4;
    float aBuf[8], bBuf[8];

    TG_LOAD_REGS(0)
    TG_STS_TILE(0)
    __syncthreads();
    int cur = 0;
    for (int kt = 0; kt < NT; kt++) {
        bool hn = (kt + 1) < NT;
        if (hn) TG_LOAD_REGS(kt + 1)
        #pragma unroll
        for (int ik = 0; ik < 2; ik++) {
            uint32_t afrag[2][4], bfrag[8][2];
            #pragma unroll
            for (int i = 0; i < 2; i++) {
                uint4 v = *reinterpret_cast<const uint4*>(
                    &AsF[cur][(((im0 + i) * 2 + ik) * 32 + lane) * 4]);
                afrag[i][0] = v.x; afrag[i][1] = v.y; afrag[i][2] = v.z; afrag[i][3] = v.w;
            }
            #pragma unroll
            for (int j = 0; j < 8; j++) {
                uint2 v = *reinterpret_cast<const uint2*>(
                    &BsF[cur][(((in0 + j) * 2 + ik) * 32 + lane) * 2]);
                bfrag[j][0] = v.x; bfrag[j][1] = v.y;
            }
            #pragma unroll
            for (int i = 0; i < 2; i++)
                #pragma unroll
                for (int j = 0; j < 8; j++)
                    mma_tf32(acc[i][j], afrag[i], bfrag[j]);
        }
        if (hn) {
            int nxt = cur ^ 1;
            TG_STS_TILE(nxt)
            __syncthreads();
            cur = nxt;
        }
    }

    // ---- epilogue ----
    const int cbase = n0 + wn * 64;
    #pragma unroll
    for (int i = 0; i < 2; i++) {
        #pragma unroll
        for (int h = 0; h < 2; h++) {
            int lr = wm * 32 + i * 16 + h * 8 + (lane >> 2);   // local row in tile
            if (MODE == 0) {
                size_t base = (size_t)(m0 + lr) * N;
                #pragma unroll
                for (int j = 0; j < 8; j++) {
                    int col = cbase + j * 8 + (lane & 3) * 2;
                    float v0 = acc[i][j][h * 2], v1 = acc[i][j][h * 2 + 1];
                    if (resid) {
                        float2 rv = *reinterpret_cast<const float2*>(&resid[base + col]);
                        v0 += rv.x; v1 += rv.y;
                    }
                    *reinterpret_cast<float2*>(&C[base + col]) = make_float2(v0, v1);
                }
            } else if (MODE == 1) {
                if (m0 + lr < ecnt) {
                    size_t base = (size_t)(eoff + m0 + lr) * N;
                    #pragma unroll
                    for (int j = 0; j < 8; j++) {
                        int col = cbase + j * 8 + (lane & 3) * 2;
                        *reinterpret_cast<float2*>(&C[base + col]) =
                            make_float2(acc[i][j][h * 2], acc[i][j][h * 2 + 1]);
                    }
                }
            } else {
                if (m0 + lr < ecnt) {
                    int sl = eoff + m0 + lr;
                    int tok = tokl[sl];
                    float ga = gatel[sl];
                    size_t base = (size_t)tok * N;
                    #pragma unroll
                    for (int j = 0; j < 8; j++) {
                        int col = cbase + j * 8 + (lane & 3) * 2;
                        atomicAdd(&C[base + col],     ga * acc[i][j][h * 2]);
                        atomicAdd(&C[base + col + 1], ga * acc[i][j][h * 2 + 1]);
                    }
                }
            }
        }
    }
}

// ---------------- RoPE (in place), pairs (d, d+32) per thread ----------------
__global__ void rope_kernel(float* __restrict__ buf, const float* __restrict__ cosp,
                            const float* __restrict__ sinp, int nheads) {
    int i = blockIdx.x * blockDim.x + threadIdx.x;
    int d = i & 31;
    int rest = i >> 5;
    int hh = rest % nheads;
    int t = rest / nheads;
    if (t >= NTOK) return;
    int s = t & (SEQ - 1);
    size_t base = (size_t)t * (nheads * HDIM) + hh * HDIM;
    float x1 = buf[base + d];
    float x2 = buf[base + d + 32];
    float c = cosp[s * HDIM + d];
    float sn = sinp[s * HDIM + d];
    buf[base + d]      = x1 * c - x2 * sn;
    buf[base + d + 32] = x2 * c + x1 * sn;
}

// ============================================================================
// Tensor-core flash attention (causal, GQA). Block: 64 queries x 1 head,
// 128 threads = 4 warps; warp owns 16 query rows. KV chunk = 64 keys.
// S = Q@K^T and O += P@V via tf32 m16n8k8; online softmax on C-frag layout.
// ============================================================================
__global__ __launch_bounds__(128)
void attn_tc_kernel(const float* __restrict__ q, const float* __restrict__ Kg,
                    const float* __restrict__ Vg, float* __restrict__ o) {
    __shared__ uint32_t Kf[4096];   // frag-packed K chunk: B for Q@K^T (n=key, k=dim)
    __shared__ uint32_t Vf[4096];   // frag-packed V chunk: B for P@V  (n=dim, k=key)

    const int b = blockIdx.z, hh = blockIdx.y, q0 = blockIdx.x * 64;
    const int tid = threadIdx.x, wid = tid >> 5, lane = tid & 31;
    const int kvh = hh >> 2;                 // H/KV = 4
    const int gid = lane >> 2, tig = lane & 3;

    // ---- Q A-frags (pre-scaled by 1/sqrt(HDIM)) ----
    uint32_t qf[8][4];
    {
        const float* qbase = q + ((size_t)(b * SEQ + q0 + wid * 16)) * DMODEL + hh * HDIM;
        #pragma unroll
        for (int ik = 0; ik < 8; ik++) {
            #pragma unroll
            for (int rr = 0; rr < 4; rr++) {
                int r = gid + 8 * (rr & 1);
                int d = ik * 8 + tig + 4 * (rr >> 1);
                qf[ik][rr] = f2tf32(qbase[(size_t)r * DMODEL + d] * 0.125f);
            }
        }
    }

    float of[8][4];
    #pragma unroll
    for (int j = 0; j < 8; j++)
        #pragma unroll
        for (int p = 0; p < 4; p++) of[j][p] = 0.f;
    float m0 = -1e30f, m1 = -1e30f, l0 = 0.f, l1 = 0.f;

    const int qrow0 = q0 + wid * 16 + gid;
    const int qrow1 = qrow0 + 8;

    // pack assignment: thread covers key = tid>>1, dims (tid&1)*32 .. +31
    const int pkey = tid >> 1;
    const int pd0  = (tid & 1) * 32;

    for (int kv0 = 0; kv0 < q0 + 64; kv0 += 64) {
        __syncthreads();   // previous chunk's reads complete before overwrite
        {
            size_t krow = ((size_t)((b * SEQ + kv0 + pkey) * NKV + kvh)) * HDIM;
            #pragma unroll
            for (int v4 = 0; v4 < 8; v4++) {
                int dbase = pd0 + v4 * 4;
                float4 kk = *reinterpret_cast<const float4*>(&Kg[krow + dbase]);
                float4 vv = *reinterpret_cast<const float4*>(&Vg[krow + dbase]);
                float kv_[4] = {kk.x, kk.y, kk.z, kk.w};
                float vv_[4] = {vv.x, vv.y, vv.z, vv.w};
                #pragma unroll
                for (int j = 0; j < 4; j++) {
                    int d = dbase + j;
                    // K: n-group=key>>3, k-group=d>>3
                    int kidx = (((pkey >> 3) * 8 + (d >> 3)) * 32 + (pkey & 7) * 4 + (d & 3)) * 2
                             + ((d >> 2) & 1);
                    Kf[kidx] = f2tf32(kv_[j]);
                    // V: n-group=d>>3, k-group=key>>3
                    int vidx = (((d >> 3) * 8 + (pkey >> 3)) * 32 + (d & 7) * 4 + (pkey & 3)) * 2
                             + ((pkey >> 2) & 1);
                    Vf[vidx] = f2tf32(vv_[j]);
                }
            }
        }
        __syncthreads();

        // ---- S = Q @ K^T  (8 n8 key-groups) ----
        float sf[8][4];
        #pragma unroll
        for (int jn = 0; jn < 8; jn++)
            #pragma unroll
            for (int p = 0; p < 4; p++) sf[jn][p] = 0.f;
        #pragma unroll
        for (int ik = 0; ik < 8; ik++) {
            #pragma unroll
            for (int jn = 0; jn < 8; jn++) {
                uint2 bb = *reinterpret_cast<const uint2*>(&Kf[((jn * 8 + ik) * 32 + lane) * 2]);
                uint32_t br[2] = {bb.x, bb.y};
                mma_tf32(sf[jn], qf[ik], br);
            }
        }

        // ---- causal mask ----
        #pragma unroll
        for (int jn = 0; jn < 8; jn++) {
            int kcol = kv0 + jn * 8 + tig * 2;
            if (kcol     > qrow0) sf[jn][0] = -1e9f;
            if (kcol + 1 > qrow0) sf[jn][1] = -1e9f;
            if (kcol     > qrow1) sf[jn][2] = -1e9f;
            if (kcol + 1 > qrow1) sf[jn][3] = -1e9f;
        }

        // ---- row max (across 4-lane group) ----
        float mn0 = m0, mn1 = m1;
        #pragma unroll
        for (int jn = 0; jn < 8; jn++) {
            mn0 = fmaxf(mn0, fmaxf(sf[jn][0], sf[jn][1]));
            mn1 = fmaxf(mn1, fmaxf(sf[jn][2], sf[jn][3]));
        }
        mn0 = fmaxf(mn0, __shfl_xor_sync(0xffffffffu, mn0, 1));
        mn0 = fmaxf(mn0, __shfl_xor_sync(0xffffffffu, mn0, 2));
        mn1 = fmaxf(mn1, __shfl_xor_sync(0xffffffffu, mn1, 1));
        mn1 = fmaxf(mn1, __shfl_xor_sync(0xffffffffu, mn1, 2));

        float fac0 = __expf(m0 - mn0), fac1 = __expf(m1 - mn1);
        l0 *= fac0; l1 *= fac1;
        #pragma unroll
        for (int jd = 0; jd < 8; jd++) {
            of[jd][0] *= fac0; of[jd][1] *= fac0;
            of[jd][2] *= fac1; of[jd][3] *= fac1;
        }
        m0 = mn0; m1 = mn1;

        // ---- P = exp(S - m); layout-convert C-frag -> A-frag; O += P @ V ----
        const int srcA = (lane & ~3) | (tig >> 1);
        const int srcB = srcA | 2;
        #pragma unroll
        for (int jn = 0; jn < 8; jn++) {
            float e0 = __expf(sf[jn][0] - mn0), e1 = __expf(sf[jn][1] - mn0);
            float e2 = __expf(sf[jn][2] - mn1), e3 = __expf(sf[jn][3] - mn1);
            l0 += e0 + e1; l1 += e2 + e3;
            float t00 = __shfl_sync(0xffffffffu, e0, srcA);
            float t01 = __shfl_sync(0xffffffffu, e1, srcA);
            float t10 = __shfl_sync(0xffffffffu, e2, srcA);
            float t11 = __shfl_sync(0xffffffffu, e3, srcA);
            float t20 = __shfl_sync(0xffffffffu, e0, srcB);
            float t21 = __shfl_sync(0xffffffffu, e1, srcB);
            float t30 = __shfl_sync(0xffffffffu, e2, srcB);
            float t31 = __shfl_sync(0xffffffffu, e3, srcB);
            uint32_t af[4];
            af[0] = f2tf32((tig & 1) ? t01 : t00);
            af[1] = f2tf32((tig & 1) ? t11 : t10);
            af[2] = f2tf32((tig & 1) ? t21 : t20);
            af[3] = f2tf32((tig & 1) ? t31 : t30);
            #pragma unroll
            for (int jd = 0; jd < 8; jd++) {
                uint2 bb = *reinterpret_cast<const uint2*>(&Vf[((jd * 8 + jn) * 32 + lane) * 2]);
                uint32_t br[2] = {bb.x, bb.y};
                mma_tf32(of[jd], af, br);
            }
        }
    }

    // ---- finalize: reduce l across the 4-lane group, normalize, store ----
    l0 += __shfl_xor_sync(0xffffffffu, l0, 1);
    l0 += __shfl_xor_sync(0xffffffffu, l0, 2);
    l1 += __shfl_xor_sync(0xffffffffu, l1, 1);
    l1 += __shfl_xor_sync(0xffffffffu, l1, 2);
    float inv0 = 1.f / l0, inv1 = 1.f / l1;
    float* obase = o + ((size_t)(b * SEQ + q0 + wid * 16)) * DMODEL + hh * HDIM;
    #pragma unroll
    for (int jd = 0; jd < 8; jd++) {
        int col = jd * 8 + tig * 2;
        *reinterpret_cast<float2*>(&obase[(size_t)gid * DMODEL + col]) =
            make_float2(of[jd][0] * inv0, of[jd][1] * inv0);
        *reinterpret_cast<float2*>(&obase[(size_t)(gid + 8) * DMODEL + col]) =
            make_float2(of[jd][2] * inv1, of[jd][3] * inv1);
    }
}

// ---------------- Router + top-2 (one warp per token) ----------------
__global__ void router_kernel(const float* __restrict__ yn, const float* __restrict__ rw,
                              int* __restrict__ topk_e, float* __restrict__ topk_w,
                              int* __restrict__ cnt) {
    int gt = blockIdx.x * blockDim.x + threadIdx.x;
    int t = gt >> 5;
    int lane = threadIdx.x & 31;
    if (t >= NTOK) return;
    const float* yr = yn + (size_t)t * DMODEL;
    float acc[NEXP];
    #pragma unroll
    for (int e = 0; e < NEXP; e++) acc[e] = 0.f;
    for (int d = lane; d < DMODEL; d += 32) {
        float x = yr[d];
        #pragma unroll
        for (int e = 0; e < NEXP; e++) acc[e] += x * rw[d * NEXP + e];
    }
    #pragma unroll
    for (int e = 0; e < NEXP; e++)
        for (int o = 16; o; o >>= 1) acc[e] += __shfl_down_sync(0xffffffffu, acc[e], o);
    if (lane == 0) {
        float v1 = -1e30f, v2 = -1e30f; int e1 = 0, e2 = 0;
        #pragma unroll
        for (int e = 0; e < NEXP; e++) {
            float v = acc[e];
            if (v > v1) { v2 = v1; e2 = e1; v1 = v; e1 = e; }
            else if (v > v2) { v2 = v; e2 = e; }
        }
        float e2v = __expf(v2 - v1);
        float den = 1.f + e2v;
        topk_e[t * 2 + 0] = e1; topk_w[t * 2 + 0] = 1.f / den;
        topk_e[t * 2 + 1] = e2; topk_w[t * 2 + 1] = e2v / den;
        atomicAdd(&cnt[e1], 1);
        atomicAdd(&cnt[e2], 1);
    }
}

__global__ void scan_kernel(const int* cnt, int* off, int* cur) {
    if (threadIdx.x == 0 && blockIdx.x == 0) {
        int run = 0;
        for (int e = 0; e < NEXP; e++) { off[e] = run; cur[e] = run; run += cnt[e]; }
    }
}

__global__ void scatter_kernel(const int* __restrict__ topk_e, const float* __restrict__ topk_w,
                               int* __restrict__ cur, int* __restrict__ tokl,
                               float* __restrict__ gatel) {
    int t = blockIdx.x * blockDim.x + threadIdx.x;
    if (t >= NTOK) return;
    #pragma unroll
    for (int j = 0; j < 2; j++) {
        int e = topk_e[t * 2 + j];
        int slot = atomicAdd(&cur[e], 1);
        tokl[slot] = t;
        gatel[slot] = topk_w[t * 2 + j];
    }
}

__global__ void silu_mul_kernel(float* __restrict__ G, const float* __restrict__ U) {
    size_t i = (size_t)blockIdx.x * blockDim.x + threadIdx.x;
    if (i < (size_t)NSLOT * FDIM) {
        float g = G[i];
        G[i] = (g / (1.f + __expf(-g))) * U[i];
    }
}

__global__ void add_kernel(const float* __restrict__ h, const float* __restrict__ moe,
                           float* __restrict__ out) {
    int i = blockIdx.x * blockDim.x + threadIdx.x;
    if (i < NTOK * DMODEL) out[i] = h[i] + moe[i];
}

// ---------------- host launcher ----------------
extern "C" void kernel_launch(void* const* d_in, const int* in_sizes, int n_in,
                              void* d_out, int out_size) {
    const float* x      = (const float*)d_in[0];
    const float* cosp   = (const float*)d_in[1];
    const float* sinp   = (const float*)d_in[2];
    // d_in[3] = mask (unused; causal computed analytically)
    const float* w_attn = (const float*)d_in[4];
    const float* w_moe  = (const float*)d_in[5];
    const float* Wq     = (const float*)d_in[6];
    const float* Wk     = (const float*)d_in[7];
    const float* Wv     = (const float*)d_in[8];
    const float* Wo     = (const float*)d_in[9];
    const float* Wr     = (const float*)d_in[10];
    const float* Wg     = (const float*)d_in[11];
    const float* Wu     = (const float*)d_in[12];
    const float* Wd     = (const float*)d_in[13];

    float* out  = (float*)d_out;
    float* outK = out + (size_t)NTOK * DMODEL;
    float* outV = outK + (size_t)NTOK * NKV * HDIM;

    float *p_xn, *p_q, *p_o, *p_h, *p_yn, *p_moe, *p_heG, *p_heU, *p_tw, *p_gate;
    int *p_te, *p_cnt, *p_off, *p_cur, *p_tok;
    cudaGetSymbolAddress((void**)&p_xn,  g_xn);
    cudaGetSymbolAddress((void**)&p_q,   g_q);
    cudaGetSymbolAddress((void**)&p_o,   g_o);
    cudaGetSymbolAddress((void**)&p_h,   g_h);
    cudaGetSymbolAddress((void**)&p_yn,  g_yn);
    cudaGetSymbolAddress((void**)&p_moe, g_moe);
    cudaGetSymbolAddress((void**)&p_heG, g_heG);
    cudaGetSymbolAddress((void**)&p_heU, g_heU);
    cudaGetSymbolAddress((void**)&p_te,  g_topk_e);
    cudaGetSymbolAddress((void**)&p_tw,  g_topk_w);
    cudaGetSymbolAddress((void**)&p_cnt, g_cnt);
    cudaGetSymbolAddress((void**)&p_off, g_off);
    cudaGetSymbolAddress((void**)&p_cur, g_cur);
    cudaGetSymbolAddress((void**)&p_tok, g_tok);
    cudaGetSymbolAddress((void**)&p_gate,g_gate);

    // 1. zero moe accumulator + counters
    zero_kernel<<<(NTOK*DMODEL + 255)/256, 256>>>(p_moe, p_cnt);
    // 2. attn rmsnorm
    rmsnorm_kernel<<<NTOK, 256>>>(x, w_attn, p_xn);
    // 3. QKV projections — all tf32 tensor cores
    tgemm_kernel<0><<<dim3(DMODEL/128, NTOK/128), 256>>>(p_xn, Wq, p_q, nullptr,
        nullptr, nullptr, nullptr, nullptr, DMODEL, DMODEL, NTOK);
    tgemm_kernel<0><<<dim3((NKV*HDIM)/128, NTOK/128), 256>>>(p_xn, Wk, outK, nullptr,
        nullptr, nullptr, nullptr, nullptr, NKV*HDIM, DMODEL, NTOK);
    tgemm_kernel<0><<<dim3((NKV*HDIM)/128, NTOK/128), 256>>>(p_xn, Wv, outV, nullptr,
        nullptr, nullptr, nullptr, nullptr, NKV*HDIM, DMODEL, NTOK);
    // 4. RoPE
    rope_kernel<<<(NTOK*NH*32)/256, 256>>>(p_q, cosp, sinp, NH);
    rope_kernel<<<(NTOK*NKV*32)/256, 256>>>(outK, cosp, sinp, NKV);
    // 5. attention (tensor-core flash)
    attn_tc_kernel<<<dim3(SEQ/64, NH, BATCH), 128>>>(p_q, outK, outV, p_o);
    // 6. output proj + residual (tf32)
    tgemm_kernel<0><<<dim3(DMODEL/128, NTOK/128), 256>>>(p_o, Wo, p_h, x,
        nullptr, nullptr, nullptr, nullptr, DMODEL, DMODEL, NTOK);
    // 7. moe rmsnorm
    rmsnorm_kernel<<<NTOK, 256>>>(p_h, w_moe, p_yn);
    // 8. router + top-2 + grouping
    router_kernel<<<NTOK/4, 128>>>(p_yn, Wr, p_te, p_tw, p_cnt);
    scan_kernel<<<1, 1>>>(p_cnt, p_off, p_cur);
    scatter_kernel<<<NTOK/256, 256>>>(p_te, p_tw, p_cur, p_tok, p_gate);
    // 9. expert gate & up projections (tf32, gathered rows), then silu*mul
    tgemm_kernel<1><<<dim3(FDIM/128, NSLOT/128, NEXP), 256>>>(p_yn, Wg, p_heG, nullptr,
        p_cnt, p_off, p_tok, nullptr, FDIM, DMODEL, 0);
    tgemm_kernel<1><<<dim3(FDIM/128, NSLOT/128, NEXP), 256>>>(p_yn, Wu, p_heU, nullptr,
        p_cnt, p_off, p_tok, nullptr, FDIM, DMODEL, 0);
    silu_mul_kernel<<<(unsigned)(((size_t)NSLOT*FDIM + 255)/256), 256>>>(p_heG, p_heU);
    // 10. down projection (tf32), gated atomic scatter into moe
    tgemm_kernel<2><<<dim3(DMODEL/128, NSLOT/128, NEXP), 256>>>(p_heG, Wd, p_moe, nullptr,
        p_cnt, p_off, p_tok, p_gate, DMODEL, FDIM, 0);
    // 11. final residual
    add_kernel<<<(NTOK*DMODEL + 255)/256, 256>>>(p_h, p_moe, out);
}